// round 12
// baseline (speedup 1.0000x reference)
#include <cuda_runtime.h>
#include <cuda_fp16.h>
#include <math.h>
#include <cstdint>

#define TOKENS  2048
#define HIDDEN  2048
#define INTER   5632
#define NEXPERTS 8
#define TOPK    2
#define NSLOTS  (TOKENS * TOPK)
#define BK 64

// ---------------- scratch ----------------
__device__ int    g_counts[NEXPERTS];
__device__ int    g_slots[NEXPERTS * NSLOTS];
__device__ __half g_xh[(size_t)TOKENS * HIDDEN];    // fp16-rounded x
__device__ float  g_gate[(size_t)NSLOTS * INTER];   // raw f32 gate
__device__ __half g_h[(size_t)NSLOTS * INTER];      // fp16 silu(g)*u
__device__ float  g_y[(size_t)NSLOTS * HIDDEN];

// ---------------- helpers ----------------
__device__ __forceinline__ uint32_t smem_u32(const void* p) {
    uint32_t a;
    asm("{ .reg .u64 t; cvta.to.shared.u64 t, %1; cvt.u32.u64 %0, t; }" : "=r"(a) : "l"(p));
    return a;
}
__device__ __forceinline__ void cp16(uint32_t dst, const void* src, int sz) {
    asm volatile("cp.async.cg.shared.global [%0], [%1], 16, %2;"
                 :: "r"(dst), "l"(src), "r"(sz) : "memory");
}
#define CP_COMMIT() asm volatile("cp.async.commit_group;" ::: "memory")
#define CP_WAIT0()  asm volatile("cp.async.wait_group 0;" ::: "memory")

__device__ __forceinline__ void ldsm4(uint32_t* r, uint32_t addr) {
    asm volatile("ldmatrix.sync.aligned.m8n8.x4.shared.b16 {%0,%1,%2,%3}, [%4];"
                 : "=r"(r[0]), "=r"(r[1]), "=r"(r[2]), "=r"(r[3]) : "r"(addr));
}
__device__ __forceinline__ void mma16(float* d, const uint32_t* a,
                                      uint32_t b0, uint32_t b1) {
    asm volatile(
        "mma.sync.aligned.m16n8k16.row.col.f32.f16.f16.f32 "
        "{%0,%1,%2,%3},{%4,%5,%6,%7},{%8,%9},{%0,%1,%2,%3};"
        : "+f"(d[0]), "+f"(d[1]), "+f"(d[2]), "+f"(d[3])
        : "r"(a[0]), "r"(a[1]), "r"(a[2]), "r"(a[3]), "r"(b0), "r"(b1));
}
__device__ __forceinline__ uint32_t pack2(float a, float b) {
    __half2 h = __floats2half2_rn(a, b);
    return *(uint32_t*)&h;
}
__device__ __forceinline__ float silu(float g) { return g / (1.f + expf(-g)); }

// ---------------- small kernels ----------------
__global__ void zero_counts_kernel() {
    if (threadIdx.x < NEXPERTS) g_counts[threadIdx.x] = 0;
}
__global__ void route_kernel(const int* __restrict__ idx) {
    int s = blockIdx.x * blockDim.x + threadIdx.x;
    if (s >= NSLOTS) return;
    int e = idx[s];
    int pos = atomicAdd(&g_counts[e], 1);
    g_slots[e * NSLOTS + pos] = s;
}
__global__ void round_x_kernel(const float* __restrict__ x) {
    int i = blockIdx.x * blockDim.x + threadIdx.x;
    if (i >= TOKENS * HIDDEN / 8) return;
    float4 v0 = *(const float4*)(x + i * 8);
    float4 v1 = *(const float4*)(x + i * 8 + 4);
    uint4 o;
    o.x = pack2(v0.x, v0.y);
    o.y = pack2(v0.z, v0.w);
    o.z = pack2(v1.x, v1.y);
    o.w = pack2(v1.z, v1.w);
    *(uint4*)(g_xh + (size_t)i * 8) = o;
}

// ================= unified grouped GEMM (fp16) =================
// CTA 128x128, BK=64. 4 warps (2x2), warp tile 64x64, 128 threads.
// smem (halves, 128B rows): A[2]@0 (16KB) | B[2]@32768 (16KB) | rows@65536
// EPI: 0 = raw f32 store; 1 = h = fp16(silu(gate)*acc)
#define G_SMEM 66048
extern __shared__ char smem[];

template<int KD, int ND, int SH, int EPI>
__global__ __launch_bounds__(128, 2)
void gemm_fp16(const __half* __restrict__ Abase,
               const float* __restrict__ Wbase,
               const float* __restrict__ Gate,
               float* __restrict__ OutF,
               __half* __restrict__ OutH) {
    const int e = blockIdx.z;
    const int count = g_counts[e];
    const int row0 = blockIdx.x * 128;
    if (row0 >= count) return;
    const int colbase = blockIdx.y * 128;

    const int tid  = threadIdx.x;
    const int lane = tid & 31;
    const int wid  = tid >> 5;
    const int q = lane & 3, gid = lane >> 2;
    const int warpm = wid >> 1;
    const int warpn = wid & 1;

    int* rowsS = (int*)(smem + 65536);
    if (tid < 128) {
        int r = row0 + tid;
        rowsS[tid] = (r < count) ? g_slots[e * NSLOTS + r] : -1;
    }
    __syncthreads();

    const uint32_t sb = smem_u32(smem);
    const float* Wp = Wbase + (size_t)e * KD * ND + colbase + tid;

    // ---- ldmatrix address precompute (XOR-folded, 128B rows of 64 halves) ----
    uint32_t BRA[4], MHA[4];
    {
        int cl = lane >> 4;
        #pragma unroll
        for (int mt = 0; mt < 4; mt++) {
            int row = warpm * 64 + mt * 16 + ((lane >> 3) & 1) * 8 + (lane & 7);
            int m3 = row & 7;
            BRA[mt] = (uint32_t)(row * 128 + ((cl ^ (m3 & 1)) << 4));
            MHA[mt] = (uint32_t)(m3 >> 1);
        }
    }
    uint32_t BRB[4], MHB[4];
    {
        int cB = (lane >> 3) & 1;
        int jt = lane >> 4;
        #pragma unroll
        for (int u = 0; u < 4; u++) {
            int row = warpn * 64 + (2 * u + jt) * 8 + (lane & 7);
            int m3 = row & 7;
            BRB[u] = (uint32_t)(row * 128 + ((cB ^ (m3 & 1)) << 4));
            MHB[u] = (uint32_t)(m3 >> 1);
        }
    }

    // ---- A loader tasks ----
    const int ar0 = tid >> 3;
    const int ag  = tid & 7;
    const uint32_t dstA0 = (uint32_t)(ar0 * 128 + ((ag ^ (ar0 & 7)) << 4));
    int aslot[8];
    const __half* pAsrc[8];
    #pragma unroll
    for (int p = 0; p < 8; p++) {
        aslot[p] = rowsS[ar0 + p * 16];
        int arow = (aslot[p] >= 0) ? (aslot[p] >> SH) : 0;
        pAsrc[p] = Abase + (size_t)arow * KD + ag * 8;
    }
    // ---- B loader: n = tid, 8 granule-tasks of 8 k-halves ----
    const uint32_t stsB0 = (uint32_t)(tid * 128);
    const int bm3 = tid & 7;

    float acc[4][8][4];
    #pragma unroll
    for (int i = 0; i < 4; i++)
        #pragma unroll
        for (int j = 0; j < 8; j++)
            #pragma unroll
            for (int k = 0; k < 4; k++) acc[i][j][k] = 0.f;

    // ---- prologue: chunk 0 ----
    #pragma unroll
    for (int p = 0; p < 8; p++)
        cp16(sb + dstA0 + p * 2048, pAsrc[p], aslot[p] >= 0 ? 16 : 0);
    CP_COMMIT();
    #pragma unroll
    for (int p = 0; p < 8; p++) {
        float f[8];
        #pragma unroll
        for (int j = 0; j < 8; j++) f[j] = Wp[(size_t)(p * 8 + j) * ND];
        uint4 o;
        o.x = pack2(f[0], f[1]); o.y = pack2(f[2], f[3]);
        o.z = pack2(f[4], f[5]); o.w = pack2(f[6], f[7]);
        *(uint4*)(smem + 32768 + stsB0 + ((p ^ bm3) << 4)) = o;
    }
    CP_WAIT0();
    __syncthreads();

    const int NCH = KD / BK;
    for (int i = 0; i < NCH; i++) {
        const int cur = i & 1, nxt = cur ^ 1;
        const bool more = (i + 1 < NCH);
        const float* Wn = Wp + (size_t)(i + 1) * BK * ND;
        char* stsNxt = smem + 32768 + nxt * 16384;

        // rolling B staging: two granule-groups in flight, 32 f32 live max
        float fA[16], fB[16];

        // group g covers granules {2g, 2g+1}
        #define LDG_GRP(buf, g)                                             \
            { _Pragma("unroll")                                             \
              for (int t = 0; t < 2; t++)                                   \
                  _Pragma("unroll")                                         \
                  for (int j = 0; j < 8; j++)                               \
                      (buf)[t * 8 + j] =                                    \
                          Wn[(size_t)((2 * (g) + t) * 8 + j) * ND]; }
        #define STS_GRP(buf, g)                                             \
            { _Pragma("unroll")                                             \
              for (int t = 0; t < 2; t++) {                                 \
                  int p = 2 * (g) + t;                                      \
                  uint4 o;                                                  \
                  o.x = pack2((buf)[t*8+0], (buf)[t*8+1]);                  \
                  o.y = pack2((buf)[t*8+2], (buf)[t*8+3]);                  \
                  o.z = pack2((buf)[t*8+4], (buf)[t*8+5]);                  \
                  o.w = pack2((buf)[t*8+6], (buf)[t*8+7]);                  \
                  *(uint4*)(stsNxt + stsB0 + ((p ^ bm3) << 4)) = o;         \
              } }

        if (more) {
            #pragma unroll
            for (int p = 0; p < 8; p++)
                cp16(sb + nxt * 16384 + dstA0 + p * 2048,
                     pAsrc[p] + (size_t)(i + 1) * BK,
                     aslot[p] >= 0 ? 16 : 0);
            CP_COMMIT();
            LDG_GRP(fA, 0);
            LDG_GRP(fB, 1);
        }

        const uint32_t bufA = sb + cur * 16384;
        const uint32_t bufB = sb + 32768 + cur * 16384;

        #define MMA_KS(ks)                                                       \
            { uint32_t a[4][4], b[4][4];                                         \
              _Pragma("unroll")                                                  \
              for (int mt = 0; mt < 4; mt++)                                     \
                  ldsm4(a[mt], bufA + BRA[mt] + (((uint32_t)(ks) ^ MHA[mt]) << 5)); \
              _Pragma("unroll")                                                  \
              for (int u = 0; u < 4; u++)                                        \
                  ldsm4(b[u], bufB + BRB[u] + (((uint32_t)(ks) ^ MHB[u]) << 5)); \
              _Pragma("unroll")                                                  \
              for (int mt = 0; mt < 4; mt++)                                     \
                  _Pragma("unroll")                                              \
                  for (int nt = 0; nt < 8; nt++)                                 \
                      mma16(acc[mt][nt], a[mt],                                  \
                            b[nt >> 1][2 * (nt & 1)], b[nt >> 1][2 * (nt & 1) + 1]); }

        MMA_KS(0);
        if (more) { STS_GRP(fA, 0); LDG_GRP(fA, 2); }
        MMA_KS(1);
        if (more) { STS_GRP(fB, 1); LDG_GRP(fB, 3); }
        MMA_KS(2);
        if (more) { STS_GRP(fA, 2); }
        MMA_KS(3);
        if (more) { STS_GRP(fB, 3); }

        #undef LDG_GRP
        #undef STS_GRP
        #undef MMA_KS

        CP_WAIT0();
        __syncthreads();
    }

    // ---- epilogue ----
    #pragma unroll
    for (int mt = 0; mt < 4; mt++) {
        #pragma unroll
        for (int half = 0; half < 2; half++) {
            int row = warpm * 64 + mt * 16 + gid + half * 8;
            int slot = rowsS[row];
            if (slot < 0) continue;
            size_t obase = (size_t)slot * ND + colbase + warpn * 64 + 2 * q;
            #pragma unroll
            for (int nt = 0; nt < 8; nt++) {
                float c0 = acc[mt][nt][half * 2 + 0];
                float c1 = acc[mt][nt][half * 2 + 1];
                if (EPI == 1) {
                    float2 gv = *(const float2*)(Gate + obase + nt * 8);
                    uint32_t h2 = pack2(silu(gv.x) * c0, silu(gv.y) * c1);
                    *(uint32_t*)(OutH + obase + nt * 8) = h2;
                } else {
                    float2 o; o.x = c0; o.y = c1;
                    *(float2*)(OutF + obase + nt * 8) = o;
                }
            }
        }
    }
}

// ---------------- combine ----------------
__global__ void combine_kernel(const float* __restrict__ ew,
                               float* __restrict__ out) {
    int i = blockIdx.x * blockDim.x + threadIdx.x;
    const int n4 = TOKENS * HIDDEN / 4;
    if (i >= n4) return;
    int t  = i / (HIDDEN / 4);
    int c4 = (i % (HIDDEN / 4)) * 4;
    float w0 = ew[t * 2 + 0];
    float w1v = ew[t * 2 + 1];
    float4 y0 = *(const float4*)(g_y + (size_t)(2 * t + 0) * HIDDEN + c4);
    float4 y1 = *(const float4*)(g_y + (size_t)(2 * t + 1) * HIDDEN + c4);
    float4 o;
    o.x = w0 * y0.x + w1v * y1.x;
    o.y = w0 * y0.y + w1v * y1.y;
    o.z = w0 * y0.z + w1v * y1.z;
    o.w = w0 * y0.w + w1v * y1.w;
    *(float4*)(out + (size_t)t * HIDDEN + c4) = o;
}

// ---------------- launch ----------------
extern "C" void kernel_launch(void* const* d_in, const int* in_sizes, int n_in,
                              void* d_out, int out_size) {
    const float* x   = (const float*)d_in[0];
    const float* ew  = (const float*)d_in[1];
    const float* w1  = (const float*)d_in[2];
    const float* w2  = (const float*)d_in[3];
    const float* w3  = (const float*)d_in[4];
    const int*   idx = (const int*)d_in[5];
    float* out = (float*)d_out;

    __half* gxh = nullptr; float* gg = nullptr; __half* gh = nullptr; float* gy = nullptr;
    cudaGetSymbolAddress((void**)&gxh, g_xh);
    cudaGetSymbolAddress((void**)&gg, g_gate);
    cudaGetSymbolAddress((void**)&gh, g_h);
    cudaGetSymbolAddress((void**)&gy, g_y);

    auto kGate = gemm_fp16<HIDDEN, INTER, 1, 0>;
    auto kUp   = gemm_fp16<HIDDEN, INTER, 1, 1>;
    auto kDown = gemm_fp16<INTER, HIDDEN, 0, 0>;
    cudaFuncSetAttribute(kGate, cudaFuncAttributeMaxDynamicSharedMemorySize, G_SMEM);
    cudaFuncSetAttribute(kUp,   cudaFuncAttributeMaxDynamicSharedMemorySize, G_SMEM);
    cudaFuncSetAttribute(kDown, cudaFuncAttributeMaxDynamicSharedMemorySize, G_SMEM);

    zero_counts_kernel<<<1, 32>>>();
    route_kernel<<<NSLOTS / 256, 256>>>(idx);
    round_x_kernel<<<(TOKENS * HIDDEN / 8 + 255) / 256, 256>>>(x);

    dim3 g1(NSLOTS / 128, INTER / 128, NEXPERTS);   // Mtile fastest for L2 reuse
    kGate<<<g1, 128, G_SMEM>>>(gxh, w1, nullptr, gg, nullptr);
    kUp  <<<g1, 128, G_SMEM>>>(gxh, w3, gg, nullptr, gh);

    dim3 g2(NSLOTS / 128, HIDDEN / 128, NEXPERTS);
    kDown<<<g2, 128, G_SMEM>>>(gh, w2, nullptr, gy, nullptr);

    combine_kernel<<<(TOKENS * HIDDEN / 4 + 255) / 256, 256>>>(ew, out);
}